// round 7
// baseline (speedup 1.0000x reference)
#include <cuda_runtime.h>
#include <math.h>

#define NTOK 100
#define XP   65
#define OTM  25
#define MP   26
#define NTHREADS 128

// smem layout (float units)
#define OFF_X    0        // X[100][65]; after decoder: Km[100][26] @0, otw[800] @2600
#define OFF_HY   6500     // H[100][65] during transformer; Y[100][33] after
#define OFF_QKV  13000    // QKV[100][20]
#define OFF_WBUF 15000    // wbuf[2720]
#define OFF_UU   17728    // uu[100]
#define OFF_VV   17828    // vv[28]
#define OFF_AA   17856    // aa[100]
#define OFF_MSK  17956    // msk[100] int
#define OFF_CNT  18056
#define SMEM_FLOATS 18060
#define SMEM_BYTES  (SMEM_FLOATS * 4)

__global__ void __launch_bounds__(NTHREADS)
jc_struc_kernel(const float* __restrict__ jc,   const int* __restrict__ flg,
                const float* __restrict__ enc_w, const float* __restrict__ enc_b,
                const float* __restrict__ B_sig, const float* __restrict__ B_jid,
                const float* __restrict__ qkv_w, const float* __restrict__ out_w,
                const float* __restrict__ out_b, const float* __restrict__ ln1_s,
                const float* __restrict__ ln1_b, const float* __restrict__ ln2_s,
                const float* __restrict__ ln2_b, const float* __restrict__ ff1_w,
                const float* __restrict__ ff1_b, const float* __restrict__ ff2_w,
                const float* __restrict__ ff2_b, const float* __restrict__ dec_w,
                const float* __restrict__ dec_b, const float* __restrict__ ot_w,
                float* __restrict__ out)
{
    extern __shared__ float sm[];
    float (*X)[XP]   = (float(*)[XP])(sm + OFF_X);
    float (*H)[XP]   = (float(*)[XP])(sm + OFF_HY);
    float (*Y)[33]   = (float(*)[33])(sm + OFF_HY);
    float (*QKV)[20] = (float(*)[20])(sm + OFF_QKV);
    float* wbuf      = sm + OFF_WBUF;
    float* Km        = sm + OFF_X;          // aliases dead X after decoder
    float* otw       = sm + OFF_X + 2600;   // aliases dead X after decoder
    float* uu        = sm + OFF_UU;
    float* vv        = sm + OFF_VV;
    float* aa        = sm + OFF_AA;
    int*   msk       = (int*)(sm + OFF_MSK);
    float* cntp      = sm + OFF_CNT;

    const int tid = threadIdx.x;
    const int s   = blockIdx.x;
    const int t   = tid;            // token owned by this thread (if tid < 100)
    const float TWO_PI = 6.283185307179586f;
    const float INV_SQRT2 = 0.7071067811865476f;

    // ================= Embedding (one thread per token) =================
    if (t < NTOK) {
        const size_t base = ((size_t)s * NTOK + t) * 3;
        const float p0 = jc[base + 0], p1 = jc[base + 1], p2 = jc[base + 2];
        const float jd = (float)(t / 4);
        msk[t] = flg[(size_t)s * NTOK + t] > 0;
        #pragma unroll 4
        for (int c = 0; c < 32; c++) {
            float proj = TWO_PI * (p0 * B_sig[c] + p1 * B_sig[32 + c] + p2 * B_sig[64 + c]);
            float ss, cs; sincosf(proj, &ss, &cs);
            float pj = TWO_PI * (jd * B_jid[c]);
            float sj, cj; sincosf(pj, &sj, &cj);
            X[t][c]      = (p0 * enc_w[c]      + p1 * enc_w[64 + c]      + p2 * enc_w[128 + c])      + enc_b[c]      + ss + sj;
            X[t][c + 32] = (p0 * enc_w[c + 32] + p1 * enc_w[64 + c + 32] + p2 * enc_w[128 + c + 32]) + enc_b[c + 32] + cs + cj;
        }
    }
    __syncthreads();
    if (tid == 0) {
        int c = 0;
        for (int i = 0; i < NTOK; i++) c += msk[i];
        *cntp = 1.0f / (float)c;
    }
    __syncthreads();

    // ================= Transformer layers =================
    for (int l = 0; l < 4; l++) {
        // --- Phase A weights: ln1_s@0, ln1_b@64, qkv (stride 18) @128 ---
        for (int i = tid; i < 1280; i += NTHREADS) {
            float v;
            if (i < 64)        v = ln1_s[l * 64 + i];
            else if (i < 128)  v = ln1_b[l * 64 + (i - 64)];
            else               v = qkv_w[l * 1152 + (i - 128)];
            wbuf[i] = v;
        }
        __syncthreads();

        // --- LN1 (fused 2-pass) + QKV matmul (acc-register ordering) ---
        if (t < NTOK) {
            float ssum = 0.f, sq = 0.f;
            #pragma unroll 8
            for (int d = 0; d < 64; d++) { float v = X[t][d]; ssum += v; sq += v * v; }
            float mu = ssum * (1.0f / 64.0f);
            float var = sq * (1.0f / 64.0f) - mu * mu;
            float rs = rsqrtf(var + 1e-5f);
            #pragma unroll 8
            for (int d = 0; d < 64; d++)
                H[t][d] = (X[t][d] - mu) * rs * wbuf[d] + wbuf[64 + d];

            float acc[18];
            #pragma unroll
            for (int c = 0; c < 18; c++) acc[c] = 0.f;
            for (int k = 0; k < 64; k++) {
                float hv = H[t][k];
                const float* wr = wbuf + 128 + k * 18;
                #pragma unroll
                for (int c = 0; c < 18; c++) acc[c] += hv * wr[c];
            }
            #pragma unroll
            for (int c = 0; c < 18; c++) QKV[t][c] = acc[c];
        }
        __syncthreads();

        // --- Phase B weights: out_w@0 (384), out_b@384, ln2_s@448, ln2_b@512 ---
        for (int i = tid; i < 576; i += NTHREADS) {
            float v;
            if (i < 384)      v = out_w[l * 384 + i];
            else if (i < 448) v = out_b[l * 64 + (i - 384)];
            else if (i < 512) v = ln2_s[l * 64 + (i - 448)];
            else              v = ln2_b[l * 64 + (i - 512)];
            wbuf[i] = v;
        }

        // --- Attention: all 3 heads in merged passes (skip masked keys) ---
        float o[6];
        if (t < NTOK) {
            float q0 = QKV[t][0], q1 = QKV[t][1], q2 = QKV[t][2];
            float q3 = QKV[t][3], q4 = QKV[t][4], q5 = QKV[t][5];
            float m0 = -3.0e38f, m1 = -3.0e38f, m2 = -3.0e38f;
            for (int j = 0; j < NTOK; j++) {
                if (msk[j]) {
                    float s0 = (q0 * QKV[j][6]  + q1 * QKV[j][7])  * INV_SQRT2;
                    float s1 = (q2 * QKV[j][8]  + q3 * QKV[j][9])  * INV_SQRT2;
                    float s2 = (q4 * QKV[j][10] + q5 * QKV[j][11]) * INV_SQRT2;
                    m0 = fmaxf(m0, s0); m1 = fmaxf(m1, s1); m2 = fmaxf(m2, s2);
                }
            }
            float d0 = 0.f, d1 = 0.f, d2 = 0.f;
            float a0 = 0.f, a1 = 0.f, a2 = 0.f, a3 = 0.f, a4 = 0.f, a5 = 0.f;
            for (int j = 0; j < NTOK; j++) {
                if (msk[j]) {
                    float s0 = (q0 * QKV[j][6]  + q1 * QKV[j][7])  * INV_SQRT2;
                    float s1 = (q2 * QKV[j][8]  + q3 * QKV[j][9])  * INV_SQRT2;
                    float s2 = (q4 * QKV[j][10] + q5 * QKV[j][11]) * INV_SQRT2;
                    float e0 = __expf(s0 - m0), e1 = __expf(s1 - m1), e2 = __expf(s2 - m2);
                    d0 += e0; d1 += e1; d2 += e2;
                    a0 += e0 * QKV[j][12]; a1 += e0 * QKV[j][13];
                    a2 += e1 * QKV[j][14]; a3 += e1 * QKV[j][15];
                    a4 += e2 * QKV[j][16]; a5 += e2 * QKV[j][17];
                }
            }
            o[0] = a0 / d0; o[1] = a1 / d0;
            o[2] = a2 / d1; o[3] = a3 / d1;
            o[4] = a4 / d2; o[5] = a5 / d2;
        }
        __syncthreads();

        // --- Out projection + residual; LN2 (fused) -> H ---
        if (t < NTOK) {
            for (int e = 0; e < 64; e++) {
                float acc = wbuf[384 + e];
                #pragma unroll
                for (int c = 0; c < 6; c++) acc += o[c] * wbuf[c * 64 + e];
                X[t][e] += acc;
            }
            float ssum = 0.f, sq = 0.f;
            #pragma unroll 8
            for (int d = 0; d < 64; d++) { float v = X[t][d]; ssum += v; sq += v * v; }
            float mu = ssum * (1.0f / 64.0f);
            float var = sq * (1.0f / 64.0f) - mu * mu;
            float rs = rsqrtf(var + 1e-5f);
            #pragma unroll 8
            for (int d = 0; d < 64; d++)
                H[t][d] = (X[t][d] - mu) * rs * wbuf[448 + d] + wbuf[512 + d];
        }
        __syncthreads();

        // --- Phase C weights: ff1_w@0, ff1_b@1024, ff2_w@1040, ff2_b@2064 ---
        for (int i = tid; i < 2128; i += NTHREADS) {
            float v;
            if (i < 1024)      v = ff1_w[l * 1024 + i];
            else if (i < 1040) v = ff1_b[l * 16 + (i - 1024)];
            else if (i < 2064) v = ff2_w[l * 1024 + (i - 1040)];
            else               v = ff2_b[l * 64 + (i - 2064)];
            wbuf[i] = v;
        }
        __syncthreads();

        // --- FFN: X += gelu(H@ff1+b1)@ff2 + b2 (acc-register ordering) ---
        if (t < NTOK) {
            float g[16];
            #pragma unroll
            for (int c = 0; c < 16; c++) g[c] = wbuf[1024 + c];
            for (int k = 0; k < 64; k++) {
                float hv = H[t][k];
                const float* wr = wbuf + k * 16;
                #pragma unroll
                for (int c = 0; c < 16; c++) g[c] += hv * wr[c];
            }
            #pragma unroll
            for (int c = 0; c < 16; c++)
                g[c] = 0.5f * g[c] * (1.0f + erff(g[c] * INV_SQRT2));
            for (int e = 0; e < 64; e++) {
                float acc = wbuf[2064 + e];
                #pragma unroll
                for (int c = 0; c < 16; c++) acc += g[c] * wbuf[1040 + c * 64 + e];
                X[t][e] += acc;
            }
        }
        __syncthreads();
    }

    // ================= Decoder: Y = relu(X @ dec_w + dec_b) =================
    for (int i = tid; i < 2080; i += NTHREADS)
        wbuf[i] = (i < 2048) ? dec_w[i] : dec_b[i - 2048];
    __syncthreads();
    if (t < NTOK) {
        float acc[32];
        #pragma unroll
        for (int c = 0; c < 32; c++) acc[c] = wbuf[2048 + c];
        for (int k = 0; k < 64; k++) {
            float xv = X[t][k];
            const float* wr = wbuf + k * 32;
            #pragma unroll
            for (int c = 0; c < 32; c++) acc[c] += xv * wr[c];
        }
        #pragma unroll
        for (int c = 0; c < 32; c++) Y[t][c] = fmaxf(acc[c], 0.f);
    }
    __syncthreads();   // X now dead; Km/otw may overwrite it

    // ================= OT kernel (convention-B band test) =================
    for (int i = tid; i < 800; i += NTHREADS) otw[i] = ot_w[i];
    __syncthreads();
    for (int idx = tid; idx < NTOK * OTM; idx += NTHREADS) {
        int i = idx / OTM, j = idx % OTM;
        float pa = __fmul_rn((float)(i + 1), 0.00999999977648258209228515625f); // fl32(1/100)
        float pb = __fmul_rn((float)(j + 1), 0.039999999105930328369140625f);   // fl32(1/25)
        float filt = (fabsf(__fsub_rn(pa, pb)) < 0.1f) ? 1.0f : 0.0f;
        float dot = 0.f;
        #pragma unroll 8
        for (int d = 0; d < 32; d++) dot += Y[i][d] * otw[j * 32 + d];
        Km[i * MP + j] = __fdiv_rn(dot * filt, 0.1f);
    }
    __syncthreads();

    // Row-max rescale: M = exp(K - r_i); linear marginals
    if (t < NTOK) {
        float r = -3.0e38f;
        #pragma unroll
        for (int j = 0; j < OTM; j++) r = fmaxf(r, Km[t * MP + j]);
        #pragma unroll
        for (int j = 0; j < OTM; j++) Km[t * MP + j] = __expf(Km[t * MP + j] - r);
        aa[t] = msk[t] ? (*cntp) : 0.0f;
    }
    if (tid < OTM) vv[tid] = 1.0f;
    __syncthreads();

    // ================= Linear-domain Sinkhorn, 100 iterations =================
    for (int it = 0; it < 100; it++) {
        if (t < NTOK) {
            float sacc = 0.f;
            #pragma unroll
            for (int j = 0; j < OTM; j++) sacc += Km[t * MP + j] * vv[j];
            uu[t] = aa[t] / sacc;
        }
        __syncthreads();
        {
            int j = tid >> 2; if (j > 24) j = 24;
            int sg = tid & 3;
            float sacc = 0.f;
            #pragma unroll 5
            for (int i = sg; i < NTOK; i += 4) sacc += Km[i * MP + j] * uu[i];
            sacc += __shfl_xor_sync(0xffffffffu, sacc, 1);
            sacc += __shfl_xor_sync(0xffffffffu, sacc, 2);
            if (sg == 0 && tid < 100) vv[j] = 0.04f / sacc;
        }
        __syncthreads();
    }

    // Fold u into M: W[i][j] = M[i][j] * u_i
    for (int idx = tid; idx < NTOK * OTM; idx += NTHREADS) {
        int i = idx / OTM, j = idx % OTM;
        Km[i * MP + j] *= uu[i];
    }
    __syncthreads();

    // ================= Output: out[s,m,d] = 25 * v_m * sum_i W[i][m] * Y[i][d] ==========
    for (int idx = tid; idx < OTM * 32; idx += NTHREADS) {
        int m = idx >> 5, d = idx & 31;
        float acc = 0.f;
        #pragma unroll 4
        for (int i = 0; i < NTOK; i++)
            acc += Km[i * MP + m] * Y[i][d];
        out[((size_t)s * OTM + m) * 32 + d] = acc * (25.0f * vv[m]);
    }
}

extern "C" void kernel_launch(void* const* d_in, const int* in_sizes, int n_in,
                              void* d_out, int out_size)
{
    (void)in_sizes; (void)n_in; (void)out_size;
    const float* jc    = (const float*)d_in[0];
    const int*   flg   = (const int*)  d_in[1];
    const float* enc_w = (const float*)d_in[2];
    const float* enc_b = (const float*)d_in[3];
    const float* B_sig = (const float*)d_in[4];
    const float* B_jid = (const float*)d_in[5];
    const float* qkv_w = (const float*)d_in[6];
    const float* out_w = (const float*)d_in[7];
    const float* out_b = (const float*)d_in[8];
    const float* ln1_s = (const float*)d_in[9];
    const float* ln1_b = (const float*)d_in[10];
    const float* ln2_s = (const float*)d_in[11];
    const float* ln2_b = (const float*)d_in[12];
    const float* ff1_w = (const float*)d_in[13];
    const float* ff1_b = (const float*)d_in[14];
    const float* ff2_w = (const float*)d_in[15];
    const float* ff2_b = (const float*)d_in[16];
    const float* dec_w = (const float*)d_in[17];
    const float* dec_b = (const float*)d_in[18];
    const float* ot_w  = (const float*)d_in[19];
    float* out = (float*)d_out;

    cudaFuncSetAttribute(jc_struc_kernel,
                         cudaFuncAttributeMaxDynamicSharedMemorySize, SMEM_BYTES);
    jc_struc_kernel<<<800, NTHREADS, SMEM_BYTES>>>(
        jc, flg, enc_w, enc_b, B_sig, B_jid, qkv_w, out_w, out_b,
        ln1_s, ln1_b, ln2_s, ln2_b, ff1_w, ff1_b, ff2_w, ff2_b,
        dec_w, dec_b, ot_w, out);
}

// round 8
// speedup vs baseline: 1.1281x; 1.1281x over previous
#include <cuda_runtime.h>
#include <math.h>

#define NTOK 100
#define XP   65
#define OTM  25
#define MP   26
#define QP   24      // QKV pitch: q@0-5, k@8-13, v@16-21 (aligned for float4/float2)
#define NTHREADS 128

// smem layout (float units), total 11952 floats = 47808 B -> 4 CTAs/SM
#define OFF_X    0        // X[100][65] (6500); decoder writes Y into X[t][0..31]
#define OFF_QKV  6500     // QKV[100][24] (2400); after transformer: otw[800]
#define OFF_WBUF 8900     // wbuf[2720]; after decoder: Km[100][26] (2600)
#define OFF_UU   11620    // uu[100]
#define OFF_VV   11720    // vv[28]
#define OFF_AA   11748    // aa[100]
#define OFF_MSK  11848    // msk[100] int
#define OFF_CNT  11948
#define SMEM_FLOATS 11952
#define SMEM_BYTES  (SMEM_FLOATS * 4)

__global__ void __launch_bounds__(NTHREADS, 4)
jc_struc_kernel(const float* __restrict__ jc,   const int* __restrict__ flg,
                const float* __restrict__ enc_w, const float* __restrict__ enc_b,
                const float* __restrict__ B_sig, const float* __restrict__ B_jid,
                const float* __restrict__ qkv_w, const float* __restrict__ out_w,
                const float* __restrict__ out_b, const float* __restrict__ ln1_s,
                const float* __restrict__ ln1_b, const float* __restrict__ ln2_s,
                const float* __restrict__ ln2_b, const float* __restrict__ ff1_w,
                const float* __restrict__ ff1_b, const float* __restrict__ ff2_w,
                const float* __restrict__ ff2_b, const float* __restrict__ dec_w,
                const float* __restrict__ dec_b, const float* __restrict__ ot_w,
                float* __restrict__ out)
{
    extern __shared__ float sm[];
    float (*X)[XP] = (float(*)[XP])(sm + OFF_X);
    float* SQ      = sm + OFF_QKV;
    float* otw     = sm + OFF_QKV;     // aliases dead QKV after transformer
    float* wbuf    = sm + OFF_WBUF;
    float* Km      = sm + OFF_WBUF;    // aliases dead wbuf after decoder
    float* uu      = sm + OFF_UU;
    float* vv      = sm + OFF_VV;
    float* aa      = sm + OFF_AA;
    int*   msk     = (int*)(sm + OFF_MSK);
    float* cntp    = sm + OFF_CNT;

    const int tid = threadIdx.x;
    const int s   = blockIdx.x;
    const int t   = tid;
    const float TWO_PI = 6.283185307179586f;
    const float INV_SQRT2 = 0.7071067811865476f;

    // ================= Embedding (one thread per token) =================
    if (t < NTOK) {
        const size_t base = ((size_t)s * NTOK + t) * 3;
        const float p0 = jc[base + 0], p1 = jc[base + 1], p2 = jc[base + 2];
        const float jd = (float)(t / 4);
        msk[t] = flg[(size_t)s * NTOK + t] > 0;
        #pragma unroll 4
        for (int c = 0; c < 32; c++) {
            float proj = TWO_PI * (p0 * B_sig[c] + p1 * B_sig[32 + c] + p2 * B_sig[64 + c]);
            float ss, cs; __sincosf(proj, &ss, &cs);
            float pj = TWO_PI * (jd * B_jid[c]);
            float sj, cj; __sincosf(pj, &sj, &cj);
            X[t][c]      = (p0 * enc_w[c]      + p1 * enc_w[64 + c]      + p2 * enc_w[128 + c])      + enc_b[c]      + ss + sj;
            X[t][c + 32] = (p0 * enc_w[c + 32] + p1 * enc_w[64 + c + 32] + p2 * enc_w[128 + c + 32]) + enc_b[c + 32] + cs + cj;
        }
    }
    __syncthreads();
    if (tid == 0) {
        int c = 0;
        for (int i = 0; i < NTOK; i++) c += msk[i];
        *cntp = 1.0f / (float)c;
    }
    __syncthreads();

    // ================= Transformer layers =================
    for (int l = 0; l < 4; l++) {
        // --- Phase A: ln1_s@0, ln1_b@64, qkv padded [64][20] @128 ---
        for (int i = tid; i < 1408; i += NTHREADS) {
            float v;
            if (i < 64)       v = ln1_s[l * 64 + i];
            else if (i < 128) v = ln1_b[l * 64 + (i - 64)];
            else {
                int k = (i - 128) / 20, c = (i - 128) % 20;
                v = (c < 18) ? qkv_w[(l * 64 + k) * 18 + c] : 0.0f;
            }
            wbuf[i] = v;
        }
        __syncthreads();

        // --- LN1 inline + QKV matmul (float4 weights) ---
        if (t < NTOK) {
            float ssum = 0.f, sq = 0.f;
            #pragma unroll 8
            for (int d = 0; d < 64; d++) { float v = X[t][d]; ssum += v; sq += v * v; }
            float mu = ssum * (1.0f / 64.0f);
            float rs = rsqrtf(sq * (1.0f / 64.0f) - mu * mu + 1e-5f);

            float acc[18];
            #pragma unroll
            for (int c = 0; c < 18; c++) acc[c] = 0.f;
            #pragma unroll 4
            for (int k = 0; k < 64; k++) {
                float h = fmaf((X[t][k] - mu) * rs, wbuf[k], wbuf[64 + k]);
                const float4* wr = (const float4*)&wbuf[128 + k * 20];
                float4 w0 = wr[0], w1 = wr[1], w2 = wr[2], w3 = wr[3], w4 = wr[4];
                acc[0] += h * w0.x;  acc[1] += h * w0.y;  acc[2] += h * w0.z;  acc[3] += h * w0.w;
                acc[4] += h * w1.x;  acc[5] += h * w1.y;  acc[6] += h * w1.z;  acc[7] += h * w1.w;
                acc[8] += h * w2.x;  acc[9] += h * w2.y;  acc[10] += h * w2.z; acc[11] += h * w2.w;
                acc[12] += h * w3.x; acc[13] += h * w3.y; acc[14] += h * w3.z; acc[15] += h * w3.w;
                acc[16] += h * w4.x; acc[17] += h * w4.y;
            }
            float* q = &SQ[t * QP];
            #pragma unroll
            for (int c = 0; c < 6; c++)  q[c]            = acc[c];
            #pragma unroll
            for (int c = 6; c < 12; c++) q[8 + (c - 6)]  = acc[c];
            #pragma unroll
            for (int c = 12; c < 18; c++) q[16 + (c - 12)] = acc[c];
        }
        __syncthreads();

        // --- Phase B+C weights (load while attention runs) ---
        for (int i = tid; i < 2704; i += NTHREADS) {
            float v;
            if (i < 384)       v = out_w[l * 384 + i];
            else if (i < 448)  v = out_b[l * 64 + (i - 384)];
            else if (i < 512)  v = ln2_s[l * 64 + (i - 448)];
            else if (i < 576)  v = ln2_b[l * 64 + (i - 512)];
            else if (i < 1600) v = ff1_w[l * 1024 + (i - 576)];
            else if (i < 1616) v = ff1_b[l * 16 + (i - 1600)];
            else if (i < 2640) v = ff2_w[l * 1024 + (i - 1616)];
            else               v = ff2_b[l * 64 + (i - 2640)];
            wbuf[i] = v;
        }

        // --- Attention: single-pass online softmax, vector K/V loads ---
        float o[6];
        if (t < NTOK) {
            const float* qp = &SQ[t * QP];
            float q0 = qp[0], q1 = qp[1], q2 = qp[2], q3 = qp[3], q4 = qp[4], q5 = qp[5];
            float m0 = -3.0e38f, m1 = -3.0e38f, m2 = -3.0e38f;
            float d0 = 0.f, d1 = 0.f, d2 = 0.f;
            float a0 = 0.f, a1 = 0.f, a2 = 0.f, a3 = 0.f, a4 = 0.f, a5 = 0.f;
            for (int j = 0; j < NTOK; j++) {
                if (!msk[j]) continue;
                const float* kj = &SQ[j * QP];
                float4 k03 = *(const float4*)(kj + 8);
                float2 k45 = *(const float2*)(kj + 12);
                float4 v03 = *(const float4*)(kj + 16);
                float2 v45 = *(const float2*)(kj + 20);
                float s0 = (q0 * k03.x + q1 * k03.y) * INV_SQRT2;
                float s1 = (q2 * k03.z + q3 * k03.w) * INV_SQRT2;
                float s2 = (q4 * k45.x + q5 * k45.y) * INV_SQRT2;
                if (s0 <= m0 && s1 <= m1 && s2 <= m2) {
                    float e0 = __expf(s0 - m0), e1 = __expf(s1 - m1), e2 = __expf(s2 - m2);
                    d0 += e0; a0 += e0 * v03.x; a1 += e0 * v03.y;
                    d1 += e1; a2 += e1 * v03.z; a3 += e1 * v03.w;
                    d2 += e2; a4 += e2 * v45.x; a5 += e2 * v45.y;
                } else {
                    float n0 = fmaxf(m0, s0), r0 = __expf(m0 - n0), e0 = __expf(s0 - n0);
                    d0 = d0 * r0 + e0; a0 = a0 * r0 + e0 * v03.x; a1 = a1 * r0 + e0 * v03.y; m0 = n0;
                    float n1 = fmaxf(m1, s1), r1 = __expf(m1 - n1), e1 = __expf(s1 - n1);
                    d1 = d1 * r1 + e1; a2 = a2 * r1 + e1 * v03.z; a3 = a3 * r1 + e1 * v03.w; m1 = n1;
                    float n2 = fmaxf(m2, s2), r2 = __expf(m2 - n2), e2 = __expf(s2 - n2);
                    d2 = d2 * r2 + e2; a4 = a4 * r2 + e2 * v45.x; a5 = a5 * r2 + e2 * v45.y; m2 = n2;
                }
            }
            o[0] = a0 / d0; o[1] = a1 / d0;
            o[2] = a2 / d1; o[3] = a3 / d1;
            o[4] = a4 / d2; o[5] = a5 / d2;
        }
        __syncthreads();

        // --- OutProj + residual; LN2 inline; FF1+gelu; FF2 + residual ---
        if (t < NTOK) {
            // out projection (e in 2 halves, float4 weights)
            #pragma unroll
            for (int eh = 0; eh < 2; eh++) {
                const int e0 = eh * 32;
                float acc[32];
                const float4* bb = (const float4*)&wbuf[384 + e0];
                #pragma unroll
                for (int i = 0; i < 8; i++) {
                    float4 b4 = bb[i];
                    acc[4*i] = b4.x; acc[4*i+1] = b4.y; acc[4*i+2] = b4.z; acc[4*i+3] = b4.w;
                }
                #pragma unroll
                for (int c = 0; c < 6; c++) {
                    float oc = o[c];
                    const float4* wr = (const float4*)&wbuf[c * 64 + e0];
                    #pragma unroll
                    for (int i = 0; i < 8; i++) {
                        float4 w4 = wr[i];
                        acc[4*i]   += oc * w4.x; acc[4*i+1] += oc * w4.y;
                        acc[4*i+2] += oc * w4.z; acc[4*i+3] += oc * w4.w;
                    }
                }
                #pragma unroll
                for (int i = 0; i < 32; i++) X[t][e0 + i] += acc[i];
            }
            // LN2 stats
            float ssum = 0.f, sq = 0.f;
            #pragma unroll 8
            for (int d = 0; d < 64; d++) { float v = X[t][d]; ssum += v; sq += v * v; }
            float mu = ssum * (1.0f / 64.0f);
            float rs = rsqrtf(sq * (1.0f / 64.0f) - mu * mu + 1e-5f);
            // FF1 (LN2 inline, float4 weights)
            float g[16];
            {
                const float4* bb = (const float4*)&wbuf[1600];
                #pragma unroll
                for (int i = 0; i < 4; i++) {
                    float4 b4 = bb[i];
                    g[4*i] = b4.x; g[4*i+1] = b4.y; g[4*i+2] = b4.z; g[4*i+3] = b4.w;
                }
            }
            #pragma unroll 4
            for (int k = 0; k < 64; k++) {
                float h = fmaf((X[t][k] - mu) * rs, wbuf[448 + k], wbuf[512 + k]);
                const float4* wr = (const float4*)&wbuf[576 + k * 16];
                float4 w0 = wr[0], w1 = wr[1], w2 = wr[2], w3 = wr[3];
                g[0] += h * w0.x;  g[1] += h * w0.y;  g[2] += h * w0.z;  g[3] += h * w0.w;
                g[4] += h * w1.x;  g[5] += h * w1.y;  g[6] += h * w1.z;  g[7] += h * w1.w;
                g[8] += h * w2.x;  g[9] += h * w2.y;  g[10] += h * w2.z; g[11] += h * w2.w;
                g[12] += h * w3.x; g[13] += h * w3.y; g[14] += h * w3.z; g[15] += h * w3.w;
            }
            #pragma unroll
            for (int c = 0; c < 16; c++)
                g[c] = 0.5f * g[c] * (1.0f + erff(g[c] * INV_SQRT2));
            // FF2 (e in 2 halves, float4 weights)
            #pragma unroll
            for (int eh = 0; eh < 2; eh++) {
                const int e0 = eh * 32;
                float acc[32];
                const float4* bb = (const float4*)&wbuf[2640 + e0];
                #pragma unroll
                for (int i = 0; i < 8; i++) {
                    float4 b4 = bb[i];
                    acc[4*i] = b4.x; acc[4*i+1] = b4.y; acc[4*i+2] = b4.z; acc[4*i+3] = b4.w;
                }
                #pragma unroll
                for (int c = 0; c < 16; c++) {
                    float gc = g[c];
                    const float4* wr = (const float4*)&wbuf[1616 + c * 64 + e0];
                    #pragma unroll
                    for (int i = 0; i < 8; i++) {
                        float4 w4 = wr[i];
                        acc[4*i]   += gc * w4.x; acc[4*i+1] += gc * w4.y;
                        acc[4*i+2] += gc * w4.z; acc[4*i+3] += gc * w4.w;
                    }
                }
                #pragma unroll
                for (int i = 0; i < 32; i++) X[t][e0 + i] += acc[i];
            }
        }
        __syncthreads();
    }

    // ================= Decoder weights + otw load =================
    for (int i = tid; i < 2080; i += NTHREADS)
        wbuf[i] = (i < 2048) ? dec_w[i] : dec_b[i - 2048];
    for (int i = tid; i < 800; i += NTHREADS) otw[i] = ot_w[i];   // QKV region (dead)
    __syncthreads();

    // ================= Decoder: Y = relu(X @ dec_w + dec_b) -> X[t][0..31] ============
    if (t < NTOK) {
        float acc[32];
        const float4* bb = (const float4*)&wbuf[2048];
        #pragma unroll
        for (int i = 0; i < 8; i++) {
            float4 b4 = bb[i];
            acc[4*i] = b4.x; acc[4*i+1] = b4.y; acc[4*i+2] = b4.z; acc[4*i+3] = b4.w;
        }
        #pragma unroll 4
        for (int k = 0; k < 64; k++) {
            float xv = X[t][k];
            const float4* wr = (const float4*)&wbuf[k * 32];
            #pragma unroll
            for (int i = 0; i < 8; i++) {
                float4 w4 = wr[i];
                acc[4*i]   += xv * w4.x; acc[4*i+1] += xv * w4.y;
                acc[4*i+2] += xv * w4.z; acc[4*i+3] += xv * w4.w;
            }
        }
        #pragma unroll
        for (int c = 0; c < 32; c++) X[t][c] = fmaxf(acc[c], 0.f);   // Y lives in X[t][0..31]
    }
    __syncthreads();   // wbuf (dec weights) dead; Km may overwrite it

    // ================= K-build (row per thread; convention-B band test) ================
    float mrow[25];
    if (t < NTOK) {
        float y[32];
        #pragma unroll
        for (int d = 0; d < 32; d++) y[d] = X[t][d];
        float pa = __fmul_rn((float)(t + 1), 0.00999999977648258209228515625f); // fl32(1/100)
        #pragma unroll
        for (int j = 0; j < OTM; j++) {
            float pb = __fmul_rn((float)(j + 1), 0.039999999105930328369140625f); // fl32(1/25)
            float kv = 0.f;
            if (fabsf(__fsub_rn(pa, pb)) < 0.1f) {
                float dot = 0.f;
                #pragma unroll
                for (int d = 0; d < 32; d++) dot += y[d] * otw[j * 32 + d];
                kv = __fdiv_rn(dot, 0.1f);
            }
            mrow[j] = kv;
        }
        float r = -3.0e38f;
        #pragma unroll
        for (int j = 0; j < OTM; j++) r = fmaxf(r, mrow[j]);
        #pragma unroll
        for (int j = 0; j < OTM; j++) mrow[j] = __expf(mrow[j] - r);
        #pragma unroll
        for (int j = 0; j < OTM; j++) Km[t * MP + j] = mrow[j];
        aa[t] = msk[t] ? (*cntp) : 0.0f;
    }
    if (tid < OTM) vv[tid] = 1.0f;
    __syncthreads();

    // ================= Linear-domain Sinkhorn, 100 iterations =================
    for (int it = 0; it < 100; it++) {
        if (t < NTOK) {
            float sacc = 0.f;
            #pragma unroll
            for (int j = 0; j < OTM; j++) sacc += mrow[j] * vv[j];
            uu[t] = aa[t] / sacc;
        }
        __syncthreads();
        {
            int j = tid >> 2; if (j > 24) j = 24;
            int sg = tid & 3;
            float sacc = 0.f;
            #pragma unroll 5
            for (int i = sg; i < NTOK; i += 4) sacc += Km[i * MP + j] * uu[i];
            sacc += __shfl_xor_sync(0xffffffffu, sacc, 1);
            sacc += __shfl_xor_sync(0xffffffffu, sacc, 2);
            if (sg == 0 && tid < 100) vv[j] = 0.04f / sacc;
        }
        __syncthreads();
    }

    // Fold u into M rows (from registers) -> Km
    if (t < NTOK) {
        float ut = uu[t];
        #pragma unroll
        for (int j = 0; j < OTM; j++) Km[t * MP + j] = mrow[j] * ut;
    }
    __syncthreads();

    // ================= Output: out[s,m,d] = 25 * v_m * sum_i W[i][m] * Y[i][d] ==========
    for (int idx = tid; idx < OTM * 32; idx += NTHREADS) {
        int m = idx >> 5, d = idx & 31;
        float acc = 0.f;
        #pragma unroll 4
        for (int i = 0; i < NTOK; i++)
            acc += Km[i * MP + m] * X[i][d];     // Y[i][d] lives in X[i][0..31]
        out[((size_t)s * OTM + m) * 32 + d] = acc * (25.0f * vv[m]);
    }
}

extern "C" void kernel_launch(void* const* d_in, const int* in_sizes, int n_in,
                              void* d_out, int out_size)
{
    (void)in_sizes; (void)n_in; (void)out_size;
    const float* jc    = (const float*)d_in[0];
    const int*   flg   = (const int*)  d_in[1];
    const float* enc_w = (const float*)d_in[2];
    const float* enc_b = (const float*)d_in[3];
    const float* B_sig = (const float*)d_in[4];
    const float* B_jid = (const float*)d_in[5];
    const float* qkv_w = (const float*)d_in[6];
    const float* out_w = (const float*)d_in[7];
    const float* out_b = (const float*)d_in[8];
    const float* ln1_s = (const float*)d_in[9];
    const float* ln1_b = (const float*)d_in[10];
    const float* ln2_s = (const float*)d_in[11];
    const float* ln2_b = (const float*)d_in[12];
    const float* ff1_w = (const float*)d_in[13];
    const float* ff1_b = (const float*)d_in[14];
    const float* ff2_w = (const float*)d_in[15];
    const float* ff2_b = (const float*)d_in[16];
    const float* dec_w = (const float*)d_in[17];
    const float* dec_b = (const float*)d_in[18];
    const float* ot_w  = (const float*)d_in[19];
    float* out = (float*)d_out;

    cudaFuncSetAttribute(jc_struc_kernel,
                         cudaFuncAttributeMaxDynamicSharedMemorySize, SMEM_BYTES);
    jc_struc_kernel<<<800, NTHREADS, SMEM_BYTES>>>(
        jc, flg, enc_w, enc_b, B_sig, B_jid, qkv_w, out_w, out_b,
        ln1_s, ln1_b, ln2_s, ln2_b, ff1_w, ff1_b, ff2_w, ff2_b,
        dec_w, dec_b, ot_w, out);
}

// round 9
// speedup vs baseline: 1.3081x; 1.1596x over previous
#include <cuda_runtime.h>
#include <math.h>

#define NTOK 100
#define XP   65
#define OTM  25
#define MP   26
#define QP   20
#define NTHREADS 128

// smem layout (float units), 11308 floats = 45232 B -> 5 CTAs/SM
#define OFF_X    0        // X[100][65]; decoder writes Y into X[t][0..31]
#define OFF_QKV  6500     // QKV[100][20]; later: otw@6500(800), uu@7400, wu@7500, vv@7600(32)
#define OFF_WBUF 8500     // wbuf[2704]; later: Km[100][26]
#define OFF_MSK  11204    // msk[100] int
#define OFF_CNT  11304
#define SMEM_FLOATS 11308
#define SMEM_BYTES  (SMEM_FLOATS * 4)

__global__ void __launch_bounds__(NTHREADS, 5)
jc_struc_kernel(const float* __restrict__ jc,   const int* __restrict__ flg,
                const float* __restrict__ enc_w, const float* __restrict__ enc_b,
                const float* __restrict__ B_sig, const float* __restrict__ B_jid,
                const float* __restrict__ qkv_w, const float* __restrict__ out_w,
                const float* __restrict__ out_b, const float* __restrict__ ln1_s,
                const float* __restrict__ ln1_b, const float* __restrict__ ln2_s,
                const float* __restrict__ ln2_b, const float* __restrict__ ff1_w,
                const float* __restrict__ ff1_b, const float* __restrict__ ff2_w,
                const float* __restrict__ ff2_b, const float* __restrict__ dec_w,
                const float* __restrict__ dec_b, const float* __restrict__ ot_w,
                float* __restrict__ out)
{
    extern __shared__ float sm[];
    float (*X)[XP] = (float(*)[XP])(sm + OFF_X);
    float* SQ   = sm + OFF_QKV;
    float* otw  = sm + OFF_QKV;          // dead QKV
    float* uu   = sm + OFF_QKV + 900;
    float* wu   = sm + OFF_QKV + 1000;
    float* vv   = sm + OFF_QKV + 1100;   // 32 entries, [25..31] = 0
    float* Pd   = sm + OFF_QKV + 900;    // aliases uu after fold
    float* wbuf = sm + OFF_WBUF;
    float* Km   = sm + OFF_WBUF;         // dead wbuf after decoder
    int*   msk  = (int*)(sm + OFF_MSK);
    float* cntp = sm + OFF_CNT;

    const int tid = threadIdx.x;
    const int lane = tid & 31;
    const int s   = blockIdx.x;
    const int t   = tid;
    const float TWO_PI = 6.283185307179586f;
    const float INV_SQRT2 = 0.7071067811865476f;
    const float INV100 = 0.00999999977648258209228515625f; // fl32(1/100)
    const float INV25  = 0.039999999105930328369140625f;   // fl32(1/25)

    // ================= Embedding =================
    if (t < NTOK) {
        const size_t base = ((size_t)s * NTOK + t) * 3;
        const float p0 = jc[base + 0], p1 = jc[base + 1], p2 = jc[base + 2];
        const float jd = (float)(t / 4);
        msk[t] = flg[(size_t)s * NTOK + t] > 0;
        #pragma unroll 4
        for (int c = 0; c < 32; c++) {
            float proj = TWO_PI * (p0 * B_sig[c] + p1 * B_sig[32 + c] + p2 * B_sig[64 + c]);
            float ss, cs; __sincosf(proj, &ss, &cs);
            float pj = TWO_PI * (jd * B_jid[c]);
            float sj, cj; __sincosf(pj, &sj, &cj);
            X[t][c]      = (p0 * enc_w[c]      + p1 * enc_w[64 + c]      + p2 * enc_w[128 + c])      + enc_b[c]      + ss + sj;
            X[t][c + 32] = (p0 * enc_w[c + 32] + p1 * enc_w[64 + c + 32] + p2 * enc_w[128 + c + 32]) + enc_b[c + 32] + cs + cj;
        }
    }
    __syncthreads();
    if (tid == 0) {
        int c = 0;
        for (int i = 0; i < NTOK; i++) c += msk[i];
        *cntp = 1.0f / (float)c;
    }
    __syncthreads();

    // ================= Transformer layers =================
    for (int l = 0; l < 4; l++) {
        // Phase A: ln1_s@0, ln1_b@64, qkv padded [64][20] @128
        for (int i = tid; i < 1408; i += NTHREADS) {
            float v;
            if (i < 64)       v = ln1_s[l * 64 + i];
            else if (i < 128) v = ln1_b[l * 64 + (i - 64)];
            else {
                int k = (i - 128) / 20, c = (i - 128) % 20;
                v = (c < 18) ? qkv_w[(l * 64 + k) * 18 + c] : 0.0f;
            }
            wbuf[i] = v;
        }
        __syncthreads();

        // LN1 inline + QKV matmul; store q, k*scale (float2), v
        if (t < NTOK) {
            float ssum = 0.f, sq = 0.f;
            #pragma unroll 8
            for (int d = 0; d < 64; d++) { float v = X[t][d]; ssum += v; sq += v * v; }
            float mu = ssum * (1.0f / 64.0f);
            float rs = rsqrtf(sq * (1.0f / 64.0f) - mu * mu + 1e-5f);

            float acc[18];
            #pragma unroll
            for (int c = 0; c < 18; c++) acc[c] = 0.f;
            #pragma unroll 4
            for (int k = 0; k < 64; k++) {
                float h = fmaf((X[t][k] - mu) * rs, wbuf[k], wbuf[64 + k]);
                const float4* wr = (const float4*)&wbuf[128 + k * 20];
                float4 w0 = wr[0], w1 = wr[1], w2 = wr[2], w3 = wr[3], w4 = wr[4];
                acc[0] += h * w0.x;  acc[1] += h * w0.y;  acc[2] += h * w0.z;  acc[3] += h * w0.w;
                acc[4] += h * w1.x;  acc[5] += h * w1.y;  acc[6] += h * w1.z;  acc[7] += h * w1.w;
                acc[8] += h * w2.x;  acc[9] += h * w2.y;  acc[10] += h * w2.z; acc[11] += h * w2.w;
                acc[12] += h * w3.x; acc[13] += h * w3.y; acc[14] += h * w3.z; acc[15] += h * w3.w;
                acc[16] += h * w4.x; acc[17] += h * w4.y;
            }
            float* q = &SQ[t * QP];
            *(float2*)(q + 0)  = make_float2(acc[0], acc[1]);
            *(float2*)(q + 2)  = make_float2(acc[2], acc[3]);
            *(float2*)(q + 4)  = make_float2(acc[4], acc[5]);
            *(float2*)(q + 6)  = make_float2(acc[6] * INV_SQRT2, acc[7] * INV_SQRT2);
            *(float2*)(q + 8)  = make_float2(acc[8] * INV_SQRT2, acc[9] * INV_SQRT2);
            *(float2*)(q + 10) = make_float2(acc[10] * INV_SQRT2, acc[11] * INV_SQRT2);
            *(float2*)(q + 12) = make_float2(acc[12], acc[13]);
            *(float2*)(q + 14) = make_float2(acc[14], acc[15]);
            *(float2*)(q + 16) = make_float2(acc[16], acc[17]);
        }
        __syncthreads();

        // Phase B+C weights (load while attention runs); ff weights via float4
        for (int i = tid; i < 576; i += NTHREADS) {
            float v;
            if (i < 384)      v = out_w[l * 384 + i];
            else if (i < 448) v = out_b[l * 64 + (i - 384)];
            else if (i < 512) v = ln2_s[l * 64 + (i - 448)];
            else              v = ln2_b[l * 64 + (i - 512)];
            wbuf[i] = v;
        }
        for (int i = tid; i < 256; i += NTHREADS)
            ((float4*)&wbuf[576])[i] = ((const float4*)&ff1_w[l * 1024])[i];
        for (int i = tid; i < 16; i += NTHREADS)
            wbuf[1600 + i] = ff1_b[l * 16 + i];
        for (int i = tid; i < 256; i += NTHREADS)
            ((float4*)&wbuf[1616])[i] = ((const float4*)&ff2_w[l * 1024])[i];
        for (int i = tid; i < 64; i += NTHREADS)
            wbuf[2640 + i] = ff2_b[l * 64 + i];

        // Attention: single-pass online softmax (k pre-scaled)
        float o[6];
        if (t < NTOK) {
            const float* qp = &SQ[t * QP];
            float q0 = qp[0], q1 = qp[1], q2 = qp[2], q3 = qp[3], q4 = qp[4], q5 = qp[5];
            float m0 = -3.0e38f, m1 = -3.0e38f, m2 = -3.0e38f;
            float d0 = 0.f, d1 = 0.f, d2 = 0.f;
            float a0 = 0.f, a1 = 0.f, a2 = 0.f, a3 = 0.f, a4 = 0.f, a5 = 0.f;
            for (int j = 0; j < NTOK; j++) {
                if (!msk[j]) continue;
                const float* kj = &SQ[j * QP];
                float2 k01 = *(const float2*)(kj + 6);
                float2 k23 = *(const float2*)(kj + 8);
                float2 k45 = *(const float2*)(kj + 10);
                float2 v01 = *(const float2*)(kj + 12);
                float2 v23 = *(const float2*)(kj + 14);
                float2 v45 = *(const float2*)(kj + 16);
                float s0 = q0 * k01.x + q1 * k01.y;
                float s1 = q2 * k23.x + q3 * k23.y;
                float s2 = q4 * k45.x + q5 * k45.y;
                if (s0 <= m0 && s1 <= m1 && s2 <= m2) {
                    float e0 = __expf(s0 - m0), e1 = __expf(s1 - m1), e2 = __expf(s2 - m2);
                    d0 += e0; a0 += e0 * v01.x; a1 += e0 * v01.y;
                    d1 += e1; a2 += e1 * v23.x; a3 += e1 * v23.y;
                    d2 += e2; a4 += e2 * v45.x; a5 += e2 * v45.y;
                } else {
                    float n0 = fmaxf(m0, s0), r0 = __expf(m0 - n0), e0 = __expf(s0 - n0);
                    d0 = d0 * r0 + e0; a0 = a0 * r0 + e0 * v01.x; a1 = a1 * r0 + e0 * v01.y; m0 = n0;
                    float n1 = fmaxf(m1, s1), r1 = __expf(m1 - n1), e1 = __expf(s1 - n1);
                    d1 = d1 * r1 + e1; a2 = a2 * r1 + e1 * v23.x; a3 = a3 * r1 + e1 * v23.y; m1 = n1;
                    float n2 = fmaxf(m2, s2), r2 = __expf(m2 - n2), e2 = __expf(s2 - n2);
                    d2 = d2 * r2 + e2; a4 = a4 * r2 + e2 * v45.x; a5 = a5 * r2 + e2 * v45.y; m2 = n2;
                }
            }
            o[0] = a0 / d0; o[1] = a1 / d0;
            o[2] = a2 / d1; o[3] = a3 / d1;
            o[4] = a4 / d2; o[5] = a5 / d2;
        }
        __syncthreads();

        if (t < NTOK) {
            // out projection + residual (16-wide chunks)
            #pragma unroll
            for (int eh = 0; eh < 4; eh++) {
                const int e0 = eh * 16;
                float acc[16];
                const float4* bb = (const float4*)&wbuf[384 + e0];
                #pragma unroll
                for (int i = 0; i < 4; i++) {
                    float4 b4 = bb[i];
                    acc[4*i] = b4.x; acc[4*i+1] = b4.y; acc[4*i+2] = b4.z; acc[4*i+3] = b4.w;
                }
                #pragma unroll
                for (int c = 0; c < 6; c++) {
                    float oc = o[c];
                    const float4* wr = (const float4*)&wbuf[c * 64 + e0];
                    #pragma unroll
                    for (int i = 0; i < 4; i++) {
                        float4 w4 = wr[i];
                        acc[4*i]   += oc * w4.x; acc[4*i+1] += oc * w4.y;
                        acc[4*i+2] += oc * w4.z; acc[4*i+3] += oc * w4.w;
                    }
                }
                #pragma unroll
                for (int i = 0; i < 16; i++) X[t][e0 + i] += acc[i];
            }
            // LN2 stats
            float ssum = 0.f, sq = 0.f;
            #pragma unroll 8
            for (int d = 0; d < 64; d++) { float v = X[t][d]; ssum += v; sq += v * v; }
            float mu = ssum * (1.0f / 64.0f);
            float rs = rsqrtf(sq * (1.0f / 64.0f) - mu * mu + 1e-5f);
            // FF1 (LN2 inline)
            float g[16];
            {
                const float4* bb = (const float4*)&wbuf[1600];
                #pragma unroll
                for (int i = 0; i < 4; i++) {
                    float4 b4 = bb[i];
                    g[4*i] = b4.x; g[4*i+1] = b4.y; g[4*i+2] = b4.z; g[4*i+3] = b4.w;
                }
            }
            #pragma unroll 4
            for (int k = 0; k < 64; k++) {
                float h = fmaf((X[t][k] - mu) * rs, wbuf[448 + k], wbuf[512 + k]);
                const float4* wr = (const float4*)&wbuf[576 + k * 16];
                float4 w0 = wr[0], w1 = wr[1], w2 = wr[2], w3 = wr[3];
                g[0] += h * w0.x;  g[1] += h * w0.y;  g[2] += h * w0.z;  g[3] += h * w0.w;
                g[4] += h * w1.x;  g[5] += h * w1.y;  g[6] += h * w1.z;  g[7] += h * w1.w;
                g[8] += h * w2.x;  g[9] += h * w2.y;  g[10] += h * w2.z; g[11] += h * w2.w;
                g[12] += h * w3.x; g[13] += h * w3.y; g[14] += h * w3.z; g[15] += h * w3.w;
            }
            #pragma unroll
            for (int c = 0; c < 16; c++)
                g[c] = 0.5f * g[c] * (1.0f + erff(g[c] * INV_SQRT2));
            // FF2 + residual (16-wide chunks)
            #pragma unroll
            for (int eh = 0; eh < 4; eh++) {
                const int e0 = eh * 16;
                float acc[16];
                const float4* bb = (const float4*)&wbuf[2640 + e0];
                #pragma unroll
                for (int i = 0; i < 4; i++) {
                    float4 b4 = bb[i];
                    acc[4*i] = b4.x; acc[4*i+1] = b4.y; acc[4*i+2] = b4.z; acc[4*i+3] = b4.w;
                }
                #pragma unroll
                for (int c = 0; c < 16; c++) {
                    float gc = g[c];
                    const float4* wr = (const float4*)&wbuf[1616 + c * 64 + e0];
                    #pragma unroll
                    for (int i = 0; i < 4; i++) {
                        float4 w4 = wr[i];
                        acc[4*i]   += gc * w4.x; acc[4*i+1] += gc * w4.y;
                        acc[4*i+2] += gc * w4.z; acc[4*i+3] += gc * w4.w;
                    }
                }
                #pragma unroll
                for (int i = 0; i < 16; i++) X[t][e0 + i] += acc[i];
            }
        }
        __syncthreads();
    }

    // ================= Decoder weights (float4) + otw =================
    for (int i = tid; i < 512; i += NTHREADS)
        ((float4*)&wbuf[0])[i] = ((const float4*)dec_w)[i];
    for (int i = tid; i < 32; i += NTHREADS)
        wbuf[2048 + i] = dec_b[i];
    for (int i = tid; i < 200; i += NTHREADS)
        ((float4*)otw)[i] = ((const float4*)ot_w)[i];
    __syncthreads();

    // ================= Decoder: Y = relu(X@dec_w + dec_b) -> X[t][0..31] ==============
    if (t < NTOK) {
        float acc[32];
        const float4* bb = (const float4*)&wbuf[2048];
        #pragma unroll
        for (int i = 0; i < 8; i++) {
            float4 b4 = bb[i];
            acc[4*i] = b4.x; acc[4*i+1] = b4.y; acc[4*i+2] = b4.z; acc[4*i+3] = b4.w;
        }
        #pragma unroll 4
        for (int k = 0; k < 64; k++) {
            float xv = X[t][k];
            const float4* wr = (const float4*)&wbuf[k * 32];
            #pragma unroll
            for (int i = 0; i < 8; i++) {
                float4 w4 = wr[i];
                acc[4*i]   += xv * w4.x; acc[4*i+1] += xv * w4.y;
                acc[4*i+2] += xv * w4.z; acc[4*i+3] += xv * w4.w;
            }
        }
        #pragma unroll
        for (int c = 0; c < 32; c++) X[t][c] = fmaxf(acc[c], 0.f);
    }
    __syncthreads();  // wbuf dead -> Km

    // ================= K-build: D = exp(K - r) - w (exactly 0 out-of-band) =============
    float mrowD[6], w_t = 0.f, areg = 0.f;
    int jlo = 0;
    #pragma unroll
    for (int k = 0; k < 6; k++) mrowD[k] = 0.f;
    if (t < NTOK) {
        float pa = __fmul_rn((float)(t + 1), INV100);
        float r = 0.f;
        for (int j = 0; j < OTM; j++) {
            float pb = __fmul_rn((float)(j + 1), INV25);
            float kv = 0.f;
            if (fabsf(__fsub_rn(pa, pb)) < 0.1f) {
                float dot = 0.f;
                #pragma unroll 8
                for (int d = 0; d < 32; d++) dot += X[t][d] * otw[j * 32 + d];
                kv = __fdiv_rn(dot, 0.1f);
            }
            r = fmaxf(r, kv);
            Km[t * MP + j] = kv;
        }
        Km[t * MP + 25] = 0.f;
        w_t = __expf(-r);
        #pragma unroll
        for (int j = 0; j < OTM; j++)
            Km[t * MP + j] = __expf(Km[t * MP + j] - r) - w_t;
        jlo = (t > 12) ? ((t - 12) >> 2) : 0;
        #pragma unroll
        for (int k = 0; k < 6; k++) {
            int jj = jlo + k;
            mrowD[k] = (jj <= 24) ? Km[t * MP + jj] : 0.f;
        }
        areg = msk[t] ? (*cntp) : 0.f;
    }
    if (tid < 32) vv[tid] = (tid < OTM) ? 1.0f : 0.0f;
    __syncthreads();

    // ================= Band-sparse linear Sinkhorn, 100 iterations =================
    {
        const int j = (t < NTOK) ? (t >> 2) : 24;
        const int sg = t & 3;
        const int ibase = 4 * j - 8;
        for (int it = 0; it < 100; it++) {
            // Vsum (per-warp shuffle reduce; all threads participate)
            float xv = vv[lane];
            xv += __shfl_xor_sync(0xffffffffu, xv, 16);
            xv += __shfl_xor_sync(0xffffffffu, xv, 8);
            xv += __shfl_xor_sync(0xffffffffu, xv, 4);
            xv += __shfl_xor_sync(0xffffffffu, xv, 2);
            xv += __shfl_xor_sync(0xffffffffu, xv, 1);
            if (t < NTOK) {
                float sacc = w_t * xv;
                #pragma unroll
                for (int k = 0; k < 6; k++) sacc += mrowD[k] * vv[jlo + k];
                float u = areg / sacc;
                uu[t] = u;
                wu[t] = w_t * u;
            }
            __syncthreads();
            // S = sum(wu) (per-warp reduce)
            float sv = wu[lane] + wu[lane + 32] + wu[lane + 64]
                     + ((lane < 4) ? wu[lane + 96] : 0.f);
            sv += __shfl_xor_sync(0xffffffffu, sv, 16);
            sv += __shfl_xor_sync(0xffffffffu, sv, 8);
            sv += __shfl_xor_sync(0xffffffffu, sv, 4);
            sv += __shfl_xor_sync(0xffffffffu, sv, 2);
            sv += __shfl_xor_sync(0xffffffffu, sv, 1);
            // column partials over band superset
            float sacc = 0.f;
            #pragma unroll
            for (int k = sg; k < 23; k += 4) {
                int i = ibase + k;
                if (i >= 0 && i < NTOK) sacc += Km[i * MP + j] * uu[i];
            }
            sacc += __shfl_xor_sync(0xffffffffu, sacc, 1);
            sacc += __shfl_xor_sync(0xffffffffu, sacc, 2);
            if (sg == 0 && t < NTOK) vv[j] = 0.04f / (sv + sacc);
            __syncthreads();
        }
    }

    // Fold u into D (band window only; rest stays 0)
    if (t < NTOK) {
        float u = uu[t];
        #pragma unroll
        for (int k = 0; k < 6; k++) {
            int jj = jlo + k;
            if (jj <= 24) Km[t * MP + jj] = mrowD[k] * u;
        }
    }
    __syncthreads();
    // Pd[d] = sum_i wu_i * Y[i][d]   (warp 0; Pd aliases uu)
    if (tid < 32) {
        float acc = 0.f;
        for (int i = 0; i < NTOK; i++) acc += wu[i] * X[i][tid];
        Pd[tid] = acc;
    }
    __syncthreads();

    // ================= Output: out[s,m,d] = 25*v_m*(Pd[d] + sum_band Du*Y) =============
    for (int idx = tid; idx < OTM * 32; idx += NTHREADS) {
        int m = idx >> 5, d = idx & 31;
        int ibase = 4 * m - 8;
        float acc = 0.f;
        #pragma unroll
        for (int k = 0; k < 23; k++) {
            int i = ibase + k;
            if (i >= 0 && i < NTOK) acc += Km[i * MP + m] * X[i][d];
        }
        out[((size_t)s * OTM + m) * 32 + d] = (Pd[d] + acc) * (25.0f * vv[m]);
    }
}

extern "C" void kernel_launch(void* const* d_in, const int* in_sizes, int n_in,
                              void* d_out, int out_size)
{
    (void)in_sizes; (void)n_in; (void)out_size;
    const float* jc    = (const float*)d_in[0];
    const int*   flg   = (const int*)  d_in[1];
    const float* enc_w = (const float*)d_in[2];
    const float* enc_b = (const float*)d_in[3];
    const float* B_sig = (const float*)d_in[4];
    const float* B_jid = (const float*)d_in[5];
    const float* qkv_w = (const float*)d_in[6];
    const float* out_w = (const float*)d_in[7];
    const float* out_b = (const float*)d_in[8];
    const float* ln1_s = (const float*)d_in[9];
    const float* ln1_b = (const float*)d_in[10];
    const float* ln2_s = (const float*)d_in[11];
    const float* ln2_b = (const float*)d_in[12];
    const float* ff1_w = (const float*)d_in[13];
    const float* ff1_b = (const float*)d_in[14];
    const float* ff2_w = (const float*)d_in[15];
    const float* ff2_b = (const float*)d_in[16];
    const float* dec_w = (const float*)d_in[17];
    const float* dec_b = (const float*)d_in[18];
    const float* ot_w  = (const float*)d_in[19];
    float* out = (float*)d_out;

    cudaFuncSetAttribute(jc_struc_kernel,
                         cudaFuncAttributeMaxDynamicSharedMemorySize, SMEM_BYTES);
    jc_struc_kernel<<<800, NTHREADS, SMEM_BYTES>>>(
        jc, flg, enc_w, enc_b, B_sig, B_jid, qkv_w, out_w, out_b,
        ln1_s, ln1_b, ln2_s, ln2_b, ff1_w, ff1_b, ff2_w, ff2_b,
        dec_w, dec_b, ot_w, out);
}

// round 10
// speedup vs baseline: 1.3507x; 1.0326x over previous
#include <cuda_runtime.h>
#include <math.h>

#define NTOK 100
#define OTM  25
#define MP   26
#define QP   18      // QKV pitch: q@0-5, k@6-11, v@12-17 (float2-aligned)
#define YPITCH 33
#define NTHREADS 128

// smem layout (float units), 8036 floats = 32144 B
#define OFF_W    0        // wbuf[<=2704] (weights); Y[100][33] after decoder
#define OFF_QKV  3300     // QKV[100][18]=1800; after transformer: otw[800]@3300, Pd[32]@4100
#define OFF_KM   5100     // Km[100][26]=2600; vlist (int) aliases during transformer
#define OFF_UU   7700     // uu[100]
#define OFF_WU   7800     // wu[100]
#define OFF_VV   7900     // vv[32] ([25..31]=0)
#define OFF_AA   7932     // aaArr[100] (1.0 if valid else 0)
#define OFF_NV   8032     // int nv
#define OFF_CNT  8033     // float 1/cnt
#define OFF_FLG  8034     // int flag
#define SMEM_FLOATS 8036
#define SMEM_BYTES  (SMEM_FLOATS * 4)

__global__ void __launch_bounds__(NTHREADS, 4)
jc_struc_kernel(const float* __restrict__ jc,   const int* __restrict__ flg,
                const float* __restrict__ enc_w, const float* __restrict__ enc_b,
                const float* __restrict__ B_sig, const float* __restrict__ B_jid,
                const float* __restrict__ qkv_w, const float* __restrict__ out_w,
                const float* __restrict__ out_b, const float* __restrict__ ln1_s,
                const float* __restrict__ ln1_b, const float* __restrict__ ln2_s,
                const float* __restrict__ ln2_b, const float* __restrict__ ff1_w,
                const float* __restrict__ ff1_b, const float* __restrict__ ff2_w,
                const float* __restrict__ ff2_b, const float* __restrict__ dec_w,
                const float* __restrict__ dec_b, const float* __restrict__ ot_w,
                float* __restrict__ out)
{
    extern __shared__ float sm[];
    float* wbuf  = sm + OFF_W;
    float* Yb    = sm + OFF_W;                 // Y[100][33] after decoder
    float* SQ    = sm + OFF_QKV;
    float* otw   = sm + OFF_QKV;               // after transformer
    float* Pd    = sm + OFF_QKV + 800;
    float* Km    = sm + OFF_KM;
    int*   vlist = (int*)(sm + OFF_KM);        // during transformer (Km dead)
    float* uu    = sm + OFF_UU;
    float* wu    = sm + OFF_WU;
    float* vv    = sm + OFF_VV;
    float* aaArr = sm + OFF_AA;
    int*   nvp   = (int*)(sm + OFF_NV);
    float* cntp  = sm + OFF_CNT;
    int*   flagp = (int*)(sm + OFF_FLG);

    const int tid  = threadIdx.x;
    const int lane = tid & 31;
    const int s    = blockIdx.x;
    const int t    = tid;
    const float TWO_PI = 6.283185307179586f;
    const float INV_SQRT2 = 0.7071067811865476f;
    const float INV100 = 0.00999999977648258209228515625f; // fl32(1/100)
    const float INV25  = 0.039999999105930328369140625f;   // fl32(1/25)

    float x[64];   // token activations live in registers for the whole transformer

    // ================= Stage embedding constants, then embed =================
    for (int i = tid; i < 384; i += NTHREADS) {
        float v;
        if (i < 96)       v = B_sig[i];
        else if (i < 128) v = B_jid[i - 96];
        else if (i < 320) v = enc_w[i - 128];
        else              v = enc_b[i - 320];
        wbuf[i] = v;
    }
    __syncthreads();
    if (t < NTOK) {
        const size_t base = ((size_t)s * NTOK + t) * 3;
        const float p0 = jc[base + 0], p1 = jc[base + 1], p2 = jc[base + 2];
        const float jd = (float)(t / 4);
        aaArr[t] = (flg[(size_t)s * NTOK + t] > 0) ? 1.0f : 0.0f;
        const float* bs = wbuf;
        const float* bj = wbuf + 96;
        const float* ew = wbuf + 128;
        const float* eb = wbuf + 320;
        #pragma unroll
        for (int c = 0; c < 32; c++) {
            float proj = TWO_PI * (p0 * bs[c] + p1 * bs[32 + c] + p2 * bs[64 + c]);
            float ss, cs; __sincosf(proj, &ss, &cs);
            float pj = TWO_PI * (jd * bj[c]);
            float sj, cj; __sincosf(pj, &sj, &cj);
            x[c]      = (p0 * ew[c]      + p1 * ew[64 + c]      + p2 * ew[128 + c])      + eb[c]      + ss + sj;
            x[c + 32] = (p0 * ew[c + 32] + p1 * ew[64 + c + 32] + p2 * ew[128 + c + 32]) + eb[c + 32] + cs + cj;
        }
    }
    __syncthreads();
    if (tid == 0) {
        int c = 0;
        for (int i = 0; i < NTOK; i++) {
            if (aaArr[i] != 0.0f) vlist[c++] = i;
        }
        *nvp = c;
        *cntp = 1.0f / (float)c;
    }
    __syncthreads();
    const int nv = *nvp;

    // ================= Transformer layers =================
    #pragma unroll 1
    for (int l = 0; l < 4; l++) {
        // Phase A: ln1_s@0, ln1_b@64, qkv padded [64][20] @128
        for (int i = tid; i < 1408; i += NTHREADS) {
            float v;
            if (i < 64)       v = ln1_s[l * 64 + i];
            else if (i < 128) v = ln1_b[l * 64 + (i - 64)];
            else {
                int k = (i - 128) / 20, c = (i - 128) % 20;
                v = (c < 18) ? qkv_w[(l * 64 + k) * 18 + c] : 0.0f;
            }
            wbuf[i] = v;
        }
        __syncthreads();

        // LN1 (regs) + QKV matmul (float4 weights)
        if (t < NTOK) {
            float ssum = 0.f, sq = 0.f;
            #pragma unroll
            for (int d = 0; d < 64; d++) { float v = x[d]; ssum += v; sq += v * v; }
            float mu = ssum * (1.0f / 64.0f);
            float rs = rsqrtf(sq * (1.0f / 64.0f) - mu * mu + 1e-5f);

            float acc[18];
            #pragma unroll
            for (int c = 0; c < 18; c++) acc[c] = 0.f;
            #pragma unroll
            for (int k = 0; k < 64; k++) {
                float h = fmaf((x[k] - mu) * rs, wbuf[k], wbuf[64 + k]);
                const float4* wr = (const float4*)&wbuf[128 + k * 20];
                float4 w0 = wr[0], w1 = wr[1], w2 = wr[2], w3 = wr[3], w4 = wr[4];
                acc[0] += h * w0.x;  acc[1] += h * w0.y;  acc[2] += h * w0.z;  acc[3] += h * w0.w;
                acc[4] += h * w1.x;  acc[5] += h * w1.y;  acc[6] += h * w1.z;  acc[7] += h * w1.w;
                acc[8] += h * w2.x;  acc[9] += h * w2.y;  acc[10] += h * w2.z; acc[11] += h * w2.w;
                acc[12] += h * w3.x; acc[13] += h * w3.y; acc[14] += h * w3.z; acc[15] += h * w3.w;
                acc[16] += h * w4.x; acc[17] += h * w4.y;
            }
            float* q = &SQ[t * QP];
            *(float2*)(q + 0)  = make_float2(acc[0], acc[1]);
            *(float2*)(q + 2)  = make_float2(acc[2], acc[3]);
            *(float2*)(q + 4)  = make_float2(acc[4], acc[5]);
            *(float2*)(q + 6)  = make_float2(acc[6] * INV_SQRT2, acc[7] * INV_SQRT2);
            *(float2*)(q + 8)  = make_float2(acc[8] * INV_SQRT2, acc[9] * INV_SQRT2);
            *(float2*)(q + 10) = make_float2(acc[10] * INV_SQRT2, acc[11] * INV_SQRT2);
            *(float2*)(q + 12) = make_float2(acc[12], acc[13]);
            *(float2*)(q + 14) = make_float2(acc[14], acc[15]);
            *(float2*)(q + 16) = make_float2(acc[16], acc[17]);
        }
        __syncthreads();

        // Phase B+C weights (load while attention runs)
        for (int i = tid; i < 576; i += NTHREADS) {
            float v;
            if (i < 384)      v = out_w[l * 384 + i];
            else if (i < 448) v = out_b[l * 64 + (i - 384)];
            else if (i < 512) v = ln2_s[l * 64 + (i - 448)];
            else              v = ln2_b[l * 64 + (i - 512)];
            wbuf[i] = v;
        }
        for (int i = tid; i < 256; i += NTHREADS)
            ((float4*)&wbuf[576])[i] = ((const float4*)&ff1_w[l * 1024])[i];
        for (int i = tid; i < 16; i += NTHREADS)
            wbuf[1600 + i] = ff1_b[l * 16 + i];
        for (int i = tid; i < 256; i += NTHREADS)
            ((float4*)&wbuf[1616])[i] = ((const float4*)&ff2_w[l * 1024])[i];
        for (int i = tid; i < 64; i += NTHREADS)
            wbuf[2640 + i] = ff2_b[l * 64 + i];

        // Attention: online softmax over compacted valid keys
        float o[6];
        if (t < NTOK) {
            const float* qp = &SQ[t * QP];
            float q0 = qp[0], q1 = qp[1], q2 = qp[2], q3 = qp[3], q4 = qp[4], q5 = qp[5];
            float m0 = -3.0e38f, m1 = -3.0e38f, m2 = -3.0e38f;
            float d0 = 0.f, d1 = 0.f, d2 = 0.f;
            float a0 = 0.f, a1 = 0.f, a2 = 0.f, a3 = 0.f, a4 = 0.f, a5 = 0.f;
            for (int jj = 0; jj < nv; jj++) {
                int j = vlist[jj];
                const float* kj = &SQ[j * QP];
                float2 k01 = *(const float2*)(kj + 6);
                float2 k23 = *(const float2*)(kj + 8);
                float2 k45 = *(const float2*)(kj + 10);
                float2 v01 = *(const float2*)(kj + 12);
                float2 v23 = *(const float2*)(kj + 14);
                float2 v45 = *(const float2*)(kj + 16);
                float s0 = q0 * k01.x + q1 * k01.y;
                float s1 = q2 * k23.x + q3 * k23.y;
                float s2 = q4 * k45.x + q5 * k45.y;
                if (s0 <= m0 && s1 <= m1 && s2 <= m2) {
                    float e0 = __expf(s0 - m0), e1 = __expf(s1 - m1), e2 = __expf(s2 - m2);
                    d0 += e0; a0 += e0 * v01.x; a1 += e0 * v01.y;
                    d1 += e1; a2 += e1 * v23.x; a3 += e1 * v23.y;
                    d2 += e2; a4 += e2 * v45.x; a5 += e2 * v45.y;
                } else {
                    float n0 = fmaxf(m0, s0), r0 = __expf(m0 - n0), e0 = __expf(s0 - n0);
                    d0 = d0 * r0 + e0; a0 = a0 * r0 + e0 * v01.x; a1 = a1 * r0 + e0 * v01.y; m0 = n0;
                    float n1 = fmaxf(m1, s1), r1 = __expf(m1 - n1), e1 = __expf(s1 - n1);
                    d1 = d1 * r1 + e1; a2 = a2 * r1 + e1 * v23.x; a3 = a3 * r1 + e1 * v23.y; m1 = n1;
                    float n2 = fmaxf(m2, s2), r2 = __expf(m2 - n2), e2 = __expf(s2 - n2);
                    d2 = d2 * r2 + e2; a4 = a4 * r2 + e2 * v45.x; a5 = a5 * r2 + e2 * v45.y; m2 = n2;
                }
            }
            o[0] = a0 / d0; o[1] = a1 / d0;
            o[2] = a2 / d1; o[3] = a3 / d1;
            o[4] = a4 / d2; o[5] = a5 / d2;
        }
        __syncthreads();

        if (t < NTOK) {
            // out projection + residual (regs)
            #pragma unroll
            for (int eh = 0; eh < 4; eh++) {
                const int e0 = eh * 16;
                float acc[16];
                const float4* bb = (const float4*)&wbuf[384 + e0];
                #pragma unroll
                for (int i = 0; i < 4; i++) {
                    float4 b4 = bb[i];
                    acc[4*i] = b4.x; acc[4*i+1] = b4.y; acc[4*i+2] = b4.z; acc[4*i+3] = b4.w;
                }
                #pragma unroll
                for (int c = 0; c < 6; c++) {
                    float oc = o[c];
                    const float4* wr = (const float4*)&wbuf[c * 64 + e0];
                    #pragma unroll
                    for (int i = 0; i < 4; i++) {
                        float4 w4 = wr[i];
                        acc[4*i]   += oc * w4.x; acc[4*i+1] += oc * w4.y;
                        acc[4*i+2] += oc * w4.z; acc[4*i+3] += oc * w4.w;
                    }
                }
                #pragma unroll
                for (int i = 0; i < 16; i++) x[e0 + i] += acc[i];
            }
            // LN2 stats (regs)
            float ssum = 0.f, sq = 0.f;
            #pragma unroll
            for (int d = 0; d < 64; d++) { float v = x[d]; ssum += v; sq += v * v; }
            float mu = ssum * (1.0f / 64.0f);
            float rs = rsqrtf(sq * (1.0f / 64.0f) - mu * mu + 1e-5f);
            // FF1
            float g[16];
            {
                const float4* bb = (const float4*)&wbuf[1600];
                #pragma unroll
                for (int i = 0; i < 4; i++) {
                    float4 b4 = bb[i];
                    g[4*i] = b4.x; g[4*i+1] = b4.y; g[4*i+2] = b4.z; g[4*i+3] = b4.w;
                }
            }
            #pragma unroll
            for (int k = 0; k < 64; k++) {
                float h = fmaf((x[k] - mu) * rs, wbuf[448 + k], wbuf[512 + k]);
                const float4* wr = (const float4*)&wbuf[576 + k * 16];
                float4 w0 = wr[0], w1 = wr[1], w2 = wr[2], w3 = wr[3];
                g[0] += h * w0.x;  g[1] += h * w0.y;  g[2] += h * w0.z;  g[3] += h * w0.w;
                g[4] += h * w1.x;  g[5] += h * w1.y;  g[6] += h * w1.z;  g[7] += h * w1.w;
                g[8] += h * w2.x;  g[9] += h * w2.y;  g[10] += h * w2.z; g[11] += h * w2.w;
                g[12] += h * w3.x; g[13] += h * w3.y; g[14] += h * w3.z; g[15] += h * w3.w;
            }
            #pragma unroll
            for (int c = 0; c < 16; c++)
                g[c] = 0.5f * g[c] * (1.0f + erff(g[c] * INV_SQRT2));
            // FF2 + residual (regs)
            #pragma unroll
            for (int eh = 0; eh < 4; eh++) {
                const int e0 = eh * 16;
                float acc[16];
                const float4* bb = (const float4*)&wbuf[2640 + e0];
                #pragma unroll
                for (int i = 0; i < 4; i++) {
                    float4 b4 = bb[i];
                    acc[4*i] = b4.x; acc[4*i+1] = b4.y; acc[4*i+2] = b4.z; acc[4*i+3] = b4.w;
                }
                #pragma unroll
                for (int c = 0; c < 16; c++) {
                    float gc = g[c];
                    const float4* wr = (const float4*)&wbuf[1616 + c * 64 + e0];
                    #pragma unroll
                    for (int i = 0; i < 4; i++) {
                        float4 w4 = wr[i];
                        acc[4*i]   += gc * w4.x; acc[4*i+1] += gc * w4.y;
                        acc[4*i+2] += gc * w4.z; acc[4*i+3] += gc * w4.w;
                    }
                }
                #pragma unroll
                for (int i = 0; i < 16; i++) x[e0 + i] += acc[i];
            }
        }
        __syncthreads();
    }

    // ================= Decoder weights + otw (QKV dead) =================
    for (int i = tid; i < 512; i += NTHREADS)
        ((float4*)&wbuf[0])[i] = ((const float4*)dec_w)[i];
    for (int i = tid; i < 32; i += NTHREADS)
        wbuf[2048 + i] = dec_b[i];
    for (int i = tid; i < 200; i += NTHREADS)
        ((float4*)otw)[i] = ((const float4*)ot_w)[i];
    __syncthreads();

    // ================= Decoder -> y regs =================
    float y[32];
    if (t < NTOK) {
        const float4* bb = (const float4*)&wbuf[2048];
        #pragma unroll
        for (int i = 0; i < 8; i++) {
            float4 b4 = bb[i];
            y[4*i] = b4.x; y[4*i+1] = b4.y; y[4*i+2] = b4.z; y[4*i+3] = b4.w;
        }
        #pragma unroll
        for (int k = 0; k < 64; k++) {
            float xv = x[k];
            const float4* wr = (const float4*)&wbuf[k * 32];
            #pragma unroll
            for (int i = 0; i < 8; i++) {
                float4 w4 = wr[i];
                y[4*i]   += xv * w4.x; y[4*i+1] += xv * w4.y;
                y[4*i+2] += xv * w4.z; y[4*i+3] += xv * w4.w;
            }
        }
        #pragma unroll
        for (int c = 0; c < 32; c++) y[c] = fmaxf(y[c], 0.f);
    }
    __syncthreads();        // all dec-weight reads done; Yb may overwrite wbuf
    if (t < NTOK) {
        #pragma unroll
        for (int c = 0; c < 32; c++) Yb[t * YPITCH + c] = y[c];
    }

    // ================= K-build: band window only, exact convention-B test ============
    float mrowD[6], w_t = 0.f, areg = 0.f;
    int jlo = 0;
    #pragma unroll
    for (int k = 0; k < 6; k++) mrowD[k] = 0.f;
    if (t < NTOK) {
        jlo = (t > 12) ? ((t - 12) >> 2) : 0;
        float pa = __fmul_rn((float)(t + 1), INV100);
        float kv[6];
        float r = 0.f;
        #pragma unroll
        for (int k = 0; k < 6; k++) {
            int j = jlo + k;
            float kvv = 0.f;
            if (j <= 24) {
                float pb = __fmul_rn((float)(j + 1), INV25);
                if (fabsf(__fsub_rn(pa, pb)) < 0.1f) {
                    float dot = 0.f;
                    const float* wj = &otw[j * 32];
                    #pragma unroll
                    for (int d = 0; d < 32; d++) dot += y[d] * wj[d];
                    kvv = __fdiv_rn(dot, 0.1f);
                }
            }
            kv[k] = kvv;
            r = fmaxf(r, kvv);
        }
        w_t = __expf(-r);
        #pragma unroll
        for (int k = 0; k < 6; k++)
            mrowD[k] = __expf(kv[k] - r) - w_t;   // exactly 0 when kv==0
        #pragma unroll
        for (int j = 0; j < MP; j++) Km[t * MP + j] = 0.f;
        #pragma unroll
        for (int k = 0; k < 6; k++) {
            int j = jlo + k;
            if (j <= 24) Km[t * MP + j] = mrowD[k];
        }
        areg = (aaArr[t] != 0.0f) ? (*cntp) : 0.f;
    }
    if (tid < 32) vv[tid] = (tid < OTM) ? 1.0f : 0.0f;
    __syncthreads();

    // ================= Band-sparse linear Sinkhorn w/ bitwise early exit =============
    {
        const int j = (t < NTOK) ? (t >> 2) : 24;
        const int sg = t & 3;
        const int ibase = 4 * j - 8;
        int done = 0;
        for (int chunk = 0; chunk < 10 && !done; chunk++) {
            float vprev = 0.f;
            if (sg == 0 && t < NTOK) vprev = vv[j];
            for (int it = 0; it < 10; it++) {
                float xv = vv[lane];
                xv += __shfl_xor_sync(0xffffffffu, xv, 16);
                xv += __shfl_xor_sync(0xffffffffu, xv, 8);
                xv += __shfl_xor_sync(0xffffffffu, xv, 4);
                xv += __shfl_xor_sync(0xffffffffu, xv, 2);
                xv += __shfl_xor_sync(0xffffffffu, xv, 1);
                if (t < NTOK) {
                    float sacc = w_t * xv;
                    #pragma unroll
                    for (int k = 0; k < 6; k++) sacc += mrowD[k] * vv[jlo + k];
                    float u = areg / sacc;
                    uu[t] = u;
                    wu[t] = w_t * u;
                }
                __syncthreads();
                float sv = wu[lane] + wu[lane + 32] + wu[lane + 64]
                         + ((lane < 4) ? wu[lane + 96] : 0.f);
                sv += __shfl_xor_sync(0xffffffffu, sv, 16);
                sv += __shfl_xor_sync(0xffffffffu, sv, 8);
                sv += __shfl_xor_sync(0xffffffffu, sv, 4);
                sv += __shfl_xor_sync(0xffffffffu, sv, 2);
                sv += __shfl_xor_sync(0xffffffffu, sv, 1);
                float sacc = 0.f;
                #pragma unroll
                for (int k = sg; k < 23; k += 4) {
                    int i = ibase + k;
                    if (i >= 0 && i < NTOK) sacc += Km[i * MP + j] * uu[i];
                }
                sacc += __shfl_xor_sync(0xffffffffu, sacc, 1);
                sacc += __shfl_xor_sync(0xffffffffu, sacc, 2);
                if (sg == 0 && t < NTOK) vv[j] = 0.04f / (sv + sacc);
                __syncthreads();
            }
            if (tid == 0) *flagp = 0;
            __syncthreads();
            if (sg == 0 && t < NTOK && vv[j] != vprev) *flagp = 1;
            __syncthreads();
            if (*flagp == 0) done = 1;
        }
    }

    // Fold u into D band (Km)
    if (t < NTOK) {
        float u = uu[t];
        #pragma unroll
        for (int k = 0; k < 6; k++) {
            int j = jlo + k;
            if (j <= 24) Km[t * MP + j] = mrowD[k] * u;
        }
    }
    __syncthreads();
    // Pd[d] = sum_i wu_i * Y[i][d]
    if (tid < 32) {
        float acc = 0.f;
        for (int i = 0; i < NTOK; i++) acc += wu[i] * Yb[i * YPITCH + tid];
        Pd[tid] = acc;
    }
    __syncthreads();

    // ================= Output =================
    for (int idx = tid; idx < OTM * 32; idx += NTHREADS) {
        int m = idx >> 5, d = idx & 31;
        int ibase = 4 * m - 8;
        float acc = 0.f;
        #pragma unroll
        for (int k = 0; k < 23; k++) {
            int i = ibase + k;
            if (i >= 0 && i < NTOK) acc += Km[i * MP + m] * Yb[i * YPITCH + d];
        }
        out[((size_t)s * OTM + m) * 32 + d] = (Pd[d] + acc) * (25.0f * vv[m]);
    }
}

extern "C" void kernel_launch(void* const* d_in, const int* in_sizes, int n_in,
                              void* d_out, int out_size)
{
    (void)in_sizes; (void)n_in; (void)out_size;
    const float* jc    = (const float*)d_in[0];
    const int*   flg   = (const int*)  d_in[1];
    const float* enc_w = (const float*)d_in[2];
    const float* enc_b = (const float*)d_in[3];
    const float* B_sig = (const float*)d_in[4];
    const float* B_jid = (const float*)d_in[5];
    const float* qkv_w = (const float*)d_in[6];
    const float* out_w = (const float*)d_in[7];
    const float* out_b = (const float*)d_in[8];
    const float* ln1_s = (const float*)d_in[9];
    const float* ln1_b = (const float*)d_in[10];
    const float* ln2_s = (const float*)d_in[11];
    const float* ln2_b = (const float*)d_in[12];
    const float* ff1_w = (const float*)d_in[13];
    const float* ff1_b = (const float*)d_in[14];
    const float* ff2_w = (const float*)d_in[15];
    const float* ff2_b = (const float*)d_in[16];
    const float* dec_w = (const float*)d_in[17];
    const float* dec_b = (const float*)d_in[18];
    const float* ot_w  = (const float*)d_in[19];
    float* out = (float*)d_out;

    cudaFuncSetAttribute(jc_struc_kernel,
                         cudaFuncAttributeMaxDynamicSharedMemorySize, SMEM_BYTES);
    jc_struc_kernel<<<800, NTHREADS, SMEM_BYTES>>>(
        jc, flg, enc_w, enc_b, B_sig, B_jid, qkv_w, out_w, out_b,
        ln1_s, ln1_b, ln2_s, ln2_b, ff1_w, ff1_b, ff2_w, ff2_b,
        dec_w, dec_b, ot_w, out);
}